// round 16
// baseline (speedup 1.0000x reference)
#include <cuda_runtime.h>
#include <cuda_fp16.h>

#define NU 100000
#define NI 50000
#define NE 200000
#define NR 64
#define D 64
#define KNB 16
#define EDGES 2000000
#define LAYERS 2
#define BB 4096
#define REG 0.0001f
#define NSEG (NI + NU)
#define NSUB (2 * BB + BB)
#define SCAN_I_BLOCKS ((NI + 1023) / 1024)
#define SCAN_U_BLOCKS ((NU + 1023) / 1024)

// ---------------- scratch ----------------------------------------------------
__device__ float  g_agg[(NU + 2 * NI) * D];     // aggu1 | aggi0 | aggi1
__device__ float  g_kg[NI * D];
__device__ float  g_ic1[NI * D];
__device__ float  g_ic2[NI * D];
__device__ float  g_rw[LAYERS * NR * D];
__device__ float  g_rb[LAYERS * NR];
__device__ float  g_wat[LAYERS * D * D];
__device__ float  g_wbt[LAYERS * D * D];
__device__ float  g_bsum[LAYERS * D];
__device__ float  g_acc;
// fp16 mirrors
__device__ __half g_h_uemb[NU * D];
__device__ __half g_h_iemb[NI * D];
__device__ __half g_h_eemb[NE * D];
__device__ __half g_h_aggu0[NU * D];
__device__ __half g_h_ic1[NI * D];
// CSR scratch (g_cnt zero-initialized at load; layer-0 gathers re-zero it)
__device__ int    g_cnt[NSEG];
__device__ int    g_off[NSEG + 1];
__device__ int    g_bs_i[256];
__device__ int    g_bs_u[256];
__device__ int2   g_csr[2 * EDGES];

// ---------------- fused fp32 -> fp16 conversion --------------------------------
#define N4_U (NU * D / 4)
#define N4_I (NI * D / 4)
#define N4_E (NE * D / 4)
#define N4_ALL (N4_U + N4_I + N4_E)
__global__ void k_tohalf(const float4* __restrict__ u, __half* __restrict__ hu,
                         const float4* __restrict__ i, __half* __restrict__ hi,
                         const float4* __restrict__ e, __half* __restrict__ he) {
    int x = blockIdx.x * 256 + threadIdx.x;
    const float4* in;
    __half* out;
    if (x < N4_U) { in = u + x; out = hu + x * 4; }
    else if (x < N4_U + N4_I) { int y = x - N4_U; in = i + y; out = hi + y * 4; }
    else if (x < N4_ALL) { int y = x - N4_U - N4_I; in = e + y; out = he + y * 4; }
    else return;
    float4 v = *in;
    __half2 a = __floats2half2_rn(v.x, v.y);
    __half2 b = __floats2half2_rn(v.z, v.w);
    uint2 o;
    o.x = *(unsigned*)&a; o.y = *(unsigned*)&b;
    *(uint2*)out = o;
}

// ---------------- merged histogram: one edge pass, 2 REDs/edge -----------------
#define EB4 ((EDGES / 4 + 255) / 256)
__global__ void k_hist(const int* __restrict__ ei, const int* __restrict__ eu,
                       int* __restrict__ cnt) {
    int base = (blockIdx.x * 256 + threadIdx.x) * 4;
    int ii[4], uu[4];
#pragma unroll
    for (int k = 0; k < 4; k++) {
        int e = base + k;
        if (e < EDGES) { ii[k] = ei[e]; uu[k] = eu[e]; }
        else ii[k] = -1;
    }
#pragma unroll
    for (int k = 0; k < 4; k++) {
        if (ii[k] < 0) continue;
        atomicAdd(&cnt[ii[k]], 1);        // no return use -> RED
        atomicAdd(&cnt[NI + uu[k]], 1);
    }
}

// ---------------- merged scan: both domains, separate lookback -----------------
__global__ void k_scan(int* __restrict__ cnt, int* __restrict__ off,
                       int* __restrict__ bs_i, int* __restrict__ bs_u) {
    __shared__ int sh[1024];
    __shared__ int s_prefix;
    int b, start, n, base, endval;
    int* bs;
    if (blockIdx.x < SCAN_I_BLOCKS) {
        b = blockIdx.x; bs = bs_i;
        start = 0; n = NI; base = 0; endval = EDGES;
    } else {
        b = blockIdx.x - SCAN_I_BLOCKS; bs = bs_u;
        start = NI; n = NU; base = EDGES; endval = 2 * EDGES;
    }
    int gid = b * 1024 + threadIdx.x;
    int v = gid < n ? cnt[start + gid] : 0;
    sh[threadIdx.x] = v;
    __syncthreads();
#pragma unroll
    for (int d = 1; d < 1024; d <<= 1) {
        int t = threadIdx.x >= d ? sh[threadIdx.x - d] : 0;
        __syncthreads();
        sh[threadIdx.x] += t;
        __syncthreads();
    }
    if (threadIdx.x == 1023) atomicExch(&bs[b], sh[1023] + 1);

    if (threadIdx.x < 32) {
        int lane = threadIdx.x;
        int sum = 0;
        volatile int* vbs = (volatile int*)bs;
        for (int i = b - 1 - lane; i >= 0; i -= 32) {
            int got;
            do { got = vbs[i]; } while (got == 0);
            sum += got - 1;
        }
#pragma unroll
        for (int o = 16; o; o >>= 1) sum += __shfl_xor_sync(0xffffffffu, sum, o);
        if (lane == 0) s_prefix = sum;
    }
    __syncthreads();
    if (gid < n) {
        int val = base + s_prefix + sh[threadIdx.x] - v;
        off[start + gid] = val;
        cnt[start + gid] = val;       // cursor for fill
    }
    if (gid == 0) off[start + n] = endval;
}

// ---------------- merged fill: one edge pass, 2 cursor atomics + 2 stores ------
__global__ void k_fill(const int* __restrict__ ei, const int* __restrict__ eu,
                       const float* __restrict__ enorm,
                       int* __restrict__ cur, int2* __restrict__ csr,
                       int* __restrict__ bs_i, int* __restrict__ bs_u) {
    if (blockIdx.x == 0 && threadIdx.x < 256) { bs_i[threadIdx.x] = 0; bs_u[threadIdx.x] = 0; }
    int base = (blockIdx.x * 256 + threadIdx.x) * 4;
    int ii[4], uu[4];
    float nrms[4];
#pragma unroll
    for (int k = 0; k < 4; k++) {
        int e = base + k;
        if (e < EDGES) { ii[k] = ei[e]; uu[k] = eu[e]; nrms[k] = enorm[e]; }
        else ii[k] = -1;
    }
    int p1[4], p2[4];
#pragma unroll
    for (int k = 0; k < 4; k++) {
        if (ii[k] < 0) continue;
        p1[k] = atomicAdd(&cur[ii[k]], 1);
        p2[k] = atomicAdd(&cur[NI + uu[k]], 1);
    }
#pragma unroll
    for (int k = 0; k < 4; k++) {
        if (ii[k] < 0) continue;
        int nb = __float_as_int(nrms[k]);
        int2 a; a.x = uu[k]; a.y = nb;
        csr[p1[k]] = a;
        int2 b2; b2.x = ii[k]; b2.y = nb;
        csr[p2[k]] = b2;
    }
}

// ---------------- rw precompute + gate weight transpose ------------------------
__global__ void k_rwprep(const float* __restrict__ remb,
                         const float* __restrict__ Wk_w,
                         const float* __restrict__ Wk_b,
                         const float* __restrict__ Wa_w,
                         const float* __restrict__ Wa_b,
                         const float* __restrict__ Wb_w,
                         const float* __restrict__ Wb_b,
                         float* __restrict__ rw, float* __restrict__ rb,
                         float* __restrict__ wat, float* __restrict__ wbt,
                         float* __restrict__ bsum, float* __restrict__ acc) {
    int b = blockIdx.x;
    if (b < LAYERS * NR) {
        if (threadIdx.x >= D) return;
        int l = b >> 6, rr = b & 63, d = threadIdx.x;
        const float* W = Wk_w + (size_t)l * D * 2 * D;
        const float* re = remb + rr * D;
        float a = 0.f;
#pragma unroll 8
        for (int o = 0; o < D; o++)
            a += re[o] * (W[o * 2 * D + d] + W[o * 2 * D + D + d]);
        rw[(l * NR + rr) * D + d] = a;
        if (d == 0) {
            const float* bb = Wk_b + l * D;
            float s = 0.f;
            for (int o = 0; o < D; o++) s += re[o] * bb[o];
            rb[l * NR + rr] = s;
        }
        if (b == 0 && d == 0) *acc = 0.f;
    } else {
        int i = (b - LAYERS * NR) * 256 + threadIdx.x;
        if (i >= LAYERS * D * D) return;
        int l = i >> 12, r = i & 4095, dd = r >> 6, o = r & 63;
        wat[i] = Wa_w[l * D * D + o * D + dd];
        wbt[i] = Wb_w[l * D * D + o * D + dd];
        if (r < D) bsum[l * D + r] = Wa_b[l * D + r] + Wb_b[l * D + r];
    }
}

// ---------------- gather core: software-pipelined (csr k+1 || rows k) ----------
__device__ __forceinline__ void gaccv(uint4 hv, float nrm, float* acc) {
    float2 f0 = __half22float2(*(__half2*)&hv.x);
    float2 f1 = __half22float2(*(__half2*)&hv.y);
    float2 f2 = __half22float2(*(__half2*)&hv.z);
    float2 f3 = __half22float2(*(__half2*)&hv.w);
    acc[0] += nrm * f0.x; acc[1] += nrm * f0.y;
    acc[2] += nrm * f1.x; acc[3] += nrm * f1.y;
    acc[4] += nrm * f2.x; acc[5] += nrm * f2.y;
    acc[6] += nrm * f3.x; acc[7] += nrm * f3.y;
}

__device__ __forceinline__ void gather_seg(const __half* __restrict__ src,
                                           const int2* __restrict__ csr,
                                           int s, int e, int g, int sub,
                                           float* acc) {
    int t = s + g;
    // pipelined main loop: batch of 4 edges per lane-group
    if (t + 12 < e) {
        int2 pr0 = __ldg(&csr[t]);
        int2 pr1 = __ldg(&csr[t + 4]);
        int2 pr2 = __ldg(&csr[t + 8]);
        int2 pr3 = __ldg(&csr[t + 12]);
        for (;;) {
            // issue row loads for current batch
            uint4 r0 = *(const uint4*)(src + (size_t)pr0.x * D + sub * 8);
            uint4 r1 = *(const uint4*)(src + (size_t)pr1.x * D + sub * 8);
            uint4 r2 = *(const uint4*)(src + (size_t)pr2.x * D + sub * 8);
            uint4 r3 = *(const uint4*)(src + (size_t)pr3.x * D + sub * 8);
            int tn = t + 16;
            bool more = (tn + 12 < e);
            int2 nx0, nx1, nx2, nx3;
            if (more) {
                // prefetch next batch's descriptors while rows are in flight
                nx0 = __ldg(&csr[tn]);
                nx1 = __ldg(&csr[tn + 4]);
                nx2 = __ldg(&csr[tn + 8]);
                nx3 = __ldg(&csr[tn + 12]);
            }
            gaccv(r0, __int_as_float(pr0.y), acc);
            gaccv(r1, __int_as_float(pr1.y), acc);
            gaccv(r2, __int_as_float(pr2.y), acc);
            gaccv(r3, __int_as_float(pr3.y), acc);
            t = tn;
            if (!more) break;
            pr0 = nx0; pr1 = nx1; pr2 = nx2; pr3 = nx3;
        }
    }
    // remainders
    if (t + 4 < e) {
        int2 p0 = __ldg(&csr[t]);
        int2 p1 = __ldg(&csr[t + 4]);
        uint4 r0 = *(const uint4*)(src + (size_t)p0.x * D + sub * 8);
        uint4 r1 = *(const uint4*)(src + (size_t)p1.x * D + sub * 8);
        gaccv(r0, __int_as_float(p0.y), acc);
        gaccv(r1, __int_as_float(p1.y), acc);
        t += 8;
    }
    if (t < e) {
        int2 p0 = __ldg(&csr[t]);
        uint4 r0 = *(const uint4*)(src + (size_t)p0.x * D + sub * 8);
        gaccv(r0, __int_as_float(p0.y), acc);
    }
}

__device__ __forceinline__ void gather_reduce(float* acc) {
#pragma unroll
    for (int k = 0; k < 8; k++) {
        acc[k] += __shfl_xor_sync(0xffffffffu, acc[k], 8);
        acc[k] += __shfl_xor_sync(0xffffffffu, acc[k], 16);
    }
}

// ---------------- layer-0 gathers (also re-zero cnt for next launch) -----------
__global__ void k_gather_i(const __half* __restrict__ usrc,
                           const int2* __restrict__ csr,
                           const int* __restrict__ off,
                           float* __restrict__ aggi,
                           int* __restrict__ cnt) {
    int w = (blockIdx.x * blockDim.x + threadIdx.x) >> 5;
    int lane = threadIdx.x & 31;
    if (w >= NI) return;
    if (lane == 0) cnt[w] = 0;
    float acc[8];
#pragma unroll
    for (int k = 0; k < 8; k++) acc[k] = 0.f;
    gather_seg(usrc, csr, off[w], off[w + 1], lane >> 3, lane & 7, acc);
    gather_reduce(acc);
    if (lane < 8) {
        float* out = aggi + (size_t)w * D;
        float4 a; a.x = acc[0]; a.y = acc[1]; a.z = acc[2]; a.w = acc[3];
        float4 b; b.x = acc[4]; b.y = acc[5]; b.z = acc[6]; b.w = acc[7];
        *(float4*)(out + lane * 8) = a;
        *(float4*)(out + lane * 8 + 4) = b;
    }
}

// user gather: fp16 output only
__global__ void k_gather_u(const __half* __restrict__ isrc,
                           const int2* __restrict__ csr,
                           const int* __restrict__ off,
                           __half* __restrict__ h_aggu,
                           int* __restrict__ cnt) {
    int w = (blockIdx.x * blockDim.x + threadIdx.x) >> 5;
    int lane = threadIdx.x & 31;
    if (w >= NU) return;
    if (lane == 0) cnt[NI + w] = 0;
    float acc[8];
#pragma unroll
    for (int k = 0; k < 8; k++) acc[k] = 0.f;
    gather_seg(isrc, csr, off[NI + w], off[NI + w + 1], lane >> 3, lane & 7, acc);
    gather_reduce(acc);
    if (lane < 8) {
        __half2 h0 = __floats2half2_rn(acc[0], acc[1]);
        __half2 h1 = __floats2half2_rn(acc[2], acc[3]);
        __half2 h2 = __floats2half2_rn(acc[4], acc[5]);
        __half2 h3 = __floats2half2_rn(acc[6], acc[7]);
        uint4 o;
        o.x = *(unsigned*)&h0; o.y = *(unsigned*)&h1;
        o.z = *(unsigned*)&h2; o.w = *(unsigned*)&h3;
        *(uint4*)(h_aggu + (size_t)w * D + lane * 8) = o;
    }
}

// ---------------- KG attention core ---------------------------------------------
__device__ __forceinline__ void attn_item(int item,
                                          const float* __restrict__ icur,
                                          const __half* __restrict__ eemb,
                                          const int* __restrict__ kg_ent,
                                          const int* __restrict__ kg_rel,
                                          const float* __restrict__ rw,
                                          const float* __restrict__ rb,
                                          float* __restrict__ kg_out,
                                          int lane) {
    float2 ic = *(const float2*)(icur + (size_t)item * D + lane * 2);
    float2 v[KNB];
    float sc[KNB];
    int base = item * KNB;
#pragma unroll
    for (int k = 0; k < KNB; k++) {
        int e = __ldg(&kg_ent[base + k]);
        int rr = __ldg(&kg_rel[base + k]);
        __half2 hv = *(const __half2*)(eemb + (size_t)e * D + lane * 2);
        v[k] = __half22float2(hv);
        float2 w = *(const float2*)(rw + rr * D + lane * 2);
        float p = v[k].x * ic.x * w.x + v[k].y * ic.y * w.y;
#pragma unroll
        for (int off = 16; off; off >>= 1) p += __shfl_xor_sync(0xffffffffu, p, off);
        p += __ldg(&rb[rr]);
        sc[k] = p >= 0.f ? p : 0.2f * p;
    }
    float m = sc[0];
#pragma unroll
    for (int k = 1; k < KNB; k++) m = fmaxf(m, sc[k]);
    float s = 0.f;
#pragma unroll
    for (int k = 0; k < KNB; k++) { sc[k] = __expf(sc[k] - m); s += sc[k]; }
    float inv = 1.f / s;
    float ax = 0.f, ay = 0.f;
#pragma unroll
    for (int k = 0; k < KNB; k++) {
        float a = sc[k] * inv;
        ax += a * v[k].x;
        ay += a * v[k].y;
    }
    float2 o;
    o.x = ax; o.y = ay;
    *(float2*)(kg_out + (size_t)item * D + lane * 2) = o;
}

__global__ void k_attn(const float* __restrict__ icur,
                       const __half* __restrict__ eemb,
                       const int* __restrict__ kg_ent,
                       const int* __restrict__ kg_rel,
                       const float* __restrict__ rw,
                       const float* __restrict__ rb,
                       float* __restrict__ kg_out) {
    int tid = threadIdx.x;
    int item = blockIdx.x * 8 + (tid >> 5);
    if (item >= NI) return;
    attn_item(item, icur, eemb, kg_ent, kg_rel, rw, rb, kg_out, tid & 31);
}

// ---------------- fused layer-1: batch-restricted gather + attention -------------
#define L1_GB ((NSUB + 7) / 8)
#define L1_AB ((2 * BB + 7) / 8)
__global__ void k_l1(const __half* __restrict__ husrc,
                     const __half* __restrict__ hisrc,
                     const int2* __restrict__ csr,
                     const int* __restrict__ off,
                     const int* __restrict__ pos,
                     const int* __restrict__ neg,
                     const int* __restrict__ user,
                     float* __restrict__ aggu,
                     float* __restrict__ aggi,
                     const float* __restrict__ icur,
                     const __half* __restrict__ eemb,
                     const int* __restrict__ kg_ent,
                     const int* __restrict__ kg_rel,
                     const float* __restrict__ rw,
                     const float* __restrict__ rb,
                     float* __restrict__ kg_out) {
    int tid = threadIdx.x;
    int warp = tid >> 5, lane = tid & 31;
    if (blockIdx.x < L1_GB) {
        int w = blockIdx.x * 8 + warp;
        if (w >= NSUB) return;
        const __half* src;
        float* out;
        int seg;
        if (w < 2 * BB) {
            int item = w < BB ? __ldg(&pos[w]) : __ldg(&neg[w - BB]);
            seg = item;
            src = husrc;
            out = aggi + (size_t)item * D;
        } else {
            int u = __ldg(&user[w - 2 * BB]);
            seg = NI + u;
            src = hisrc;
            out = aggu + (size_t)u * D;
        }
        float acc[8];
#pragma unroll
        for (int k = 0; k < 8; k++) acc[k] = 0.f;
        gather_seg(src, csr, off[seg], off[seg + 1], lane >> 3, lane & 7, acc);
        gather_reduce(acc);
        if (lane < 8) {
            float4 a; a.x = acc[0]; a.y = acc[1]; a.z = acc[2]; a.w = acc[3];
            float4 b; b.x = acc[4]; b.y = acc[5]; b.z = acc[6]; b.w = acc[7];
            *(float4*)(out + lane * 8) = a;
            *(float4*)(out + lane * 8 + 4) = b;
        }
    } else {
        int w = (blockIdx.x - L1_GB) * 8 + warp;
        if (w >= 2 * BB) return;
        int item = w < BB ? __ldg(&pos[w]) : __ldg(&neg[w - BB]);
        attn_item(item, icur, eemb, kg_ent, kg_rel, rw, rb, kg_out, lane);
    }
}

// ---------------- gate + item update ----------------------------------------------
#define G_ITEMS 64
#define G_PITCH 66
#define G_SMEM ((2 * D * G_PITCH + 2 * G_ITEMS * D + D) * sizeof(float))

template <bool SUB>
__device__ __forceinline__ void gate_body(const float* __restrict__ kg,
                                          const float* __restrict__ aggi,
                                          const float* __restrict__ wat,
                                          const float* __restrict__ wbt,
                                          const float* __restrict__ bsum,
                                          float* __restrict__ inew,
                                          __half* __restrict__ hout,
                                          const int* __restrict__ pos,
                                          const int* __restrict__ neg) {
    extern __shared__ float sm[];
    float* sWa = sm;
    float* sWb = sWa + D * G_PITCH;
    float* skg = sWb + D * G_PITCH;
    float* sag = skg + G_ITEMS * D;
    float* sb  = sag + G_ITEMS * D;
    __shared__ int sidx[G_ITEMS];

    int tid = threadIdx.x;
    int base = blockIdx.x * G_ITEMS;

    for (int i = tid; i < D * D; i += 256) {
        int dd = i >> 6, o = i & 63;
        sWa[dd * G_PITCH + o] = wat[i];
        sWb[dd * G_PITCH + o] = wbt[i];
    }
    if (tid < D) sb[tid] = bsum[tid];
    if (tid < G_ITEMS) {
        int j = base + tid;
        int gidx;
        if (SUB) gidx = j < BB ? __ldg(&pos[j]) : __ldg(&neg[j - BB]);
        else { gidx = j; if (gidx >= NI) gidx = NI - 1; }
        sidx[tid] = gidx;
    }
    __syncthreads();

    for (int i = tid; i < G_ITEMS * (D / 4); i += 256) {
        int it = i >> 4, c = i & 15;
        int gidx = sidx[it];
        ((float4*)skg)[it * 16 + c] = ((const float4*)kg)[(size_t)gidx * 16 + c];
        ((float4*)sag)[it * 16 + c] = ((const float4*)aggi)[(size_t)gidx * 16 + c];
    }
    __syncthreads();

    int warp = tid >> 5, lane = tid & 31;
    float2 acc[8];
#pragma unroll
    for (int j = 0; j < 8; j++) { acc[j].x = 0.f; acc[j].y = 0.f; }

    for (int d = 0; d < D; d += 2) {
        float2 wa0 = *(const float2*)(sWa + d * G_PITCH + 2 * lane);
        float2 wa1 = *(const float2*)(sWa + (d + 1) * G_PITCH + 2 * lane);
        float2 wb0 = *(const float2*)(sWb + d * G_PITCH + 2 * lane);
        float2 wb1 = *(const float2*)(sWb + (d + 1) * G_PITCH + 2 * lane);
#pragma unroll
        for (int j = 0; j < 8; j++) {
            int it = warp * 8 + j;
            float2 xk = *(const float2*)(skg + it * D + d);
            float2 xa = *(const float2*)(sag + it * D + d);
            acc[j].x += xk.x * wa0.x + xk.y * wa1.x + xa.x * wb0.x + xa.y * wb1.x;
            acc[j].y += xk.x * wa0.y + xk.y * wa1.y + xa.x * wb0.y + xa.y * wb1.y;
        }
    }

    float2 b2 = *(const float2*)(sb + 2 * lane);
#pragma unroll
    for (int j = 0; j < 8; j++) {
        int it = warp * 8 + j;
        if (!SUB && base + it >= NI) break;
        float gx = 1.f / (1.f + __expf(-(acc[j].x + b2.x)));
        float gy = 1.f / (1.f + __expf(-(acc[j].y + b2.y)));
        float2 kv = *(const float2*)(skg + it * D + 2 * lane);
        float2 av = *(const float2*)(sag + it * D + 2 * lane);
        float2 o2;
        o2.x = gx * kv.x + (1.f - gx) * av.x;
        o2.y = gy * kv.y + (1.f - gy) * av.y;
        int gidx = sidx[it];
        ((float2*)(inew + (size_t)gidx * D))[lane] = o2;
        if (!SUB && hout != nullptr) {
            __half2 h = __floats2half2_rn(o2.x, o2.y);
            ((__half2*)(hout + (size_t)gidx * D))[lane] = h;
        }
    }
}

__global__ void k_gate(const float* __restrict__ kg,
                       const float* __restrict__ aggi,
                       const float* __restrict__ wat,
                       const float* __restrict__ wbt,
                       const float* __restrict__ bsum,
                       float* __restrict__ inew,
                       __half* __restrict__ hout) {
    gate_body<false>(kg, aggi, wat, wbt, bsum, inew, hout, nullptr, nullptr);
}

__global__ void k_gate_sub(const float* __restrict__ kg,
                           const float* __restrict__ aggi,
                           const float* __restrict__ wat,
                           const float* __restrict__ wbt,
                           const float* __restrict__ bsum,
                           float* __restrict__ inew,
                           const int* __restrict__ pos,
                           const int* __restrict__ neg) {
    gate_body<true>(kg, aggi, wat, wbt, bsum, inew, nullptr, pos, neg);
}

// ---------------- loss (aggu0 read from fp16 mirror) -----------------------------
__global__ void k_loss(const float* __restrict__ uemb,
                       const __half* __restrict__ h_aggu0,
                       const float* __restrict__ aggu1,
                       const float* __restrict__ iemb,
                       const float* __restrict__ ic1,
                       const float* __restrict__ ic2,
                       const int* __restrict__ user,
                       const int* __restrict__ pos,
                       const int* __restrict__ neg,
                       float* __restrict__ acc) {
    int b = (blockIdx.x * blockDim.x + threadIdx.x) >> 5;
    int lane = threadIdx.x & 31;
    if (b >= BB) return;
    size_t u = (size_t)user[b] * D;
    size_t p = (size_t)pos[b] * D;
    size_t n = (size_t)neg[b] * D;

    int d = lane * 2;
    float2 ua = *(const float2*)(uemb + u + d);
    float2 ub = __half22float2(*(const __half2*)(h_aggu0 + u + d));
    float2 uc = *(const float2*)(aggu1 + u + d);
    float2 pa = *(const float2*)(iemb + p + d);
    float2 pb = *(const float2*)(ic1 + p + d);
    float2 pc = *(const float2*)(ic2 + p + d);
    float2 na = *(const float2*)(iemb + n + d);
    float2 nb = *(const float2*)(ic1 + n + d);
    float2 nc = *(const float2*)(ic2 + n + d);
    float uex = ua.x + ub.x + uc.x, uey = ua.y + ub.y + uc.y;
    float pex = pa.x + pb.x + pc.x, pey = pa.y + pb.y + pc.y;
    float nex = na.x + nb.x + nc.x, ney = na.y + nb.y + nc.y;
    float ps = uex * pex + uey * pey;
    float ns = uex * nex + uey * ney;
    float l2 = uex * uex + uey * uey + pex * pex + pey * pey + nex * nex + ney * ney;
#pragma unroll
    for (int off = 16; off; off >>= 1) {
        ps += __shfl_xor_sync(0xffffffffu, ps, off);
        ns += __shfl_xor_sync(0xffffffffu, ns, off);
        l2 += __shfl_xor_sync(0xffffffffu, l2, off);
    }
    if (lane == 0) {
        float x = ps - ns;
        float sg = 1.f / (1.f + expf(-x));
        float term = -logf(sg + 1e-10f) + REG * l2;
        atomicAdd(acc, term);
    }
}

__global__ void k_final(const float* __restrict__ acc, float* __restrict__ out) {
    out[0] = acc[0] * (1.f / (float)BB);
}

// ---------------- launch ----------------------------------------------------------
extern "C" void kernel_launch(void* const* d_in, const int* in_sizes, int n_in,
                              void* d_out, int out_size) {
    const float* uemb  = (const float*)d_in[0];
    const float* iemb  = (const float*)d_in[1];
    const float* eemb  = (const float*)d_in[2];
    const float* remb  = (const float*)d_in[3];
    const float* Wk_w  = (const float*)d_in[4];
    const float* Wk_b  = (const float*)d_in[5];
    const float* Wa_w  = (const float*)d_in[6];
    const float* Wa_b  = (const float*)d_in[7];
    const float* Wb_w  = (const float*)d_in[8];
    const float* Wb_b  = (const float*)d_in[9];
    const float* enorm = (const float*)d_in[10];
    const int* user    = (const int*)d_in[11];
    const int* pos     = (const int*)d_in[12];
    const int* neg     = (const int*)d_in[13];
    const int* eu      = (const int*)d_in[14];
    const int* ei      = (const int*)d_in[15];
    const int* kg_rel  = (const int*)d_in[16];
    const int* kg_ent  = (const int*)d_in[17];

    float *agg, *kg, *ic1, *ic2, *rw, *rb, *wat, *wbt, *bsum, *acc;
    int *cnt, *off, *bs_i, *bs_u;
    int2 *csr;
    __half *h_uemb, *h_iemb, *h_eemb, *h_aggu0, *h_ic1;
    cudaGetSymbolAddress((void**)&agg, g_agg);
    cudaGetSymbolAddress((void**)&kg, g_kg);
    cudaGetSymbolAddress((void**)&ic1, g_ic1);
    cudaGetSymbolAddress((void**)&ic2, g_ic2);
    cudaGetSymbolAddress((void**)&rw, g_rw);
    cudaGetSymbolAddress((void**)&rb, g_rb);
    cudaGetSymbolAddress((void**)&wat, g_wat);
    cudaGetSymbolAddress((void**)&wbt, g_wbt);
    cudaGetSymbolAddress((void**)&bsum, g_bsum);
    cudaGetSymbolAddress((void**)&acc, g_acc);
    cudaGetSymbolAddress((void**)&cnt, g_cnt);
    cudaGetSymbolAddress((void**)&off, g_off);
    cudaGetSymbolAddress((void**)&bs_i, g_bs_i);
    cudaGetSymbolAddress((void**)&bs_u, g_bs_u);
    cudaGetSymbolAddress((void**)&csr, g_csr);
    cudaGetSymbolAddress((void**)&h_uemb, g_h_uemb);
    cudaGetSymbolAddress((void**)&h_iemb, g_h_iemb);
    cudaGetSymbolAddress((void**)&h_eemb, g_h_eemb);
    cudaGetSymbolAddress((void**)&h_aggu0, g_h_aggu0);
    cudaGetSymbolAddress((void**)&h_ic1, g_h_ic1);

    float* aggu1 = agg;
    float* aggi0 = agg + (size_t)NU * D;
    float* aggi1 = agg + (size_t)NU * D + (size_t)NI * D;

    cudaFuncSetAttribute(k_gate, cudaFuncAttributeMaxDynamicSharedMemorySize,
                         (int)G_SMEM);
    cudaFuncSetAttribute(k_gate_sub, cudaFuncAttributeMaxDynamicSharedMemorySize,
                         (int)G_SMEM);

    static cudaStream_t s1 = nullptr, s2 = nullptr, s3 = nullptr;
    static cudaEvent_t e_fork, e_th, e_attn, e_fill, e_gu, e_done;
    if (s1 == nullptr) {
        cudaStreamCreateWithFlags(&s1, cudaStreamNonBlocking);
        cudaStreamCreateWithFlags(&s2, cudaStreamNonBlocking);
        cudaStreamCreateWithFlags(&s3, cudaStreamNonBlocking);
        cudaEventCreateWithFlags(&e_fork, cudaEventDisableTiming);
        cudaEventCreateWithFlags(&e_th, cudaEventDisableTiming);
        cudaEventCreateWithFlags(&e_attn, cudaEventDisableTiming);
        cudaEventCreateWithFlags(&e_fill, cudaEventDisableTiming);
        cudaEventCreateWithFlags(&e_gu, cudaEventDisableTiming);
        cudaEventCreateWithFlags(&e_done, cudaEventDisableTiming);
    }

    // ---- fork ----
    cudaEventRecord(e_fork, 0);
    cudaStreamWaitEvent(s1, e_fork, 0);
    cudaStreamWaitEvent(s3, e_fork, 0);

    // ---- s3: embeddings/weights arm ----
    k_tohalf<<<(N4_ALL + 255) / 256, 256, 0, s3>>>(
        (const float4*)uemb, h_uemb,
        (const float4*)iemb, h_iemb,
        (const float4*)eemb, h_eemb);
    cudaEventRecord(e_th, s3);
    k_rwprep<<<LAYERS * NR + (LAYERS * D * D + 255) / 256, 256, 0, s3>>>(
        remb, Wk_w, Wk_b, Wa_w, Wa_b, Wb_w, Wb_b, rw, rb, wat, wbt, bsum, acc);
    k_attn<<<(NI + 7) / 8, 256, 0, s3>>>(iemb, h_eemb, kg_ent, kg_rel, rw, rb, kg);
    cudaEventRecord(e_attn, s3);

    // ---- s1: merged CSR build ----
    k_hist<<<EB4, 256, 0, s1>>>(ei, eu, cnt);
    k_scan<<<SCAN_I_BLOCKS + SCAN_U_BLOCKS, 1024, 0, s1>>>(cnt, off, bs_i, bs_u);
    k_fill<<<EB4, 256, 0, s1>>>(ei, eu, enorm, cnt, csr, bs_i, bs_u);
    cudaEventRecord(e_fill, s1);
    cudaStreamWaitEvent(s1, e_th, 0);
    k_gather_i<<<(NI + 7) / 8, 256, 0, s1>>>(h_uemb, csr, off, aggi0, cnt);

    // ---- s2: user gather in parallel with item gather ----
    cudaStreamWaitEvent(s2, e_fill, 0);
    cudaStreamWaitEvent(s2, e_th, 0);
    k_gather_u<<<(NU + 7) / 8, 256, 0, s2>>>(h_iemb, csr, off, h_aggu0, cnt);
    cudaEventRecord(e_gu, s2);

    // ---- join on s1 ----
    cudaStreamWaitEvent(s1, e_attn, 0);
    k_gate<<<(NI + G_ITEMS - 1) / G_ITEMS, 256, G_SMEM, s1>>>(
        kg, aggi0, wat, wbt, bsum, ic1, h_ic1);
    cudaStreamWaitEvent(s1, e_gu, 0);
    k_l1<<<L1_GB + L1_AB, 256, 0, s1>>>(h_aggu0, h_ic1, csr, off, pos, neg, user,
                                        aggu1, aggi1,
                                        ic1, h_eemb, kg_ent, kg_rel,
                                        rw + NR * D, rb + NR, kg);
    k_gate_sub<<<2 * BB / G_ITEMS, 256, G_SMEM, s1>>>(kg, aggi1,
                                                      wat + D * D, wbt + D * D,
                                                      bsum + D, ic2, pos, neg);
    k_loss<<<(BB * 32 + 255) / 256, 256, 0, s1>>>(uemb, h_aggu0, aggu1,
                                                  iemb, ic1, ic2,
                                                  user, pos, neg, acc);
    k_final<<<1, 1, 0, s1>>>(acc, (float*)d_out);
    cudaEventRecord(e_done, s1);

    // ---- join back to caller's stream ----
    cudaStreamWaitEvent(0, e_done, 0);
}

// round 17
// speedup vs baseline: 1.0239x; 1.0239x over previous
#include <cuda_runtime.h>
#include <cuda_fp16.h>

#define NU 100000
#define NI 50000
#define NE 200000
#define NR 64
#define D 64
#define KNB 16
#define EDGES 2000000
#define LAYERS 2
#define BB 4096
#define REG 0.0001f
#define NSEG (NI + NU)
#define NSUB (2 * BB + BB)
#define SCAN_I_BLOCKS ((NI + 1023) / 1024)
#define SCAN_U_BLOCKS ((NU + 1023) / 1024)

// ---------------- scratch ----------------------------------------------------
__device__ float  g_agg[(NU + 2 * NI) * D];     // aggu1 | aggi0 | aggi1
__device__ float  g_kg[NI * D];
__device__ float  g_ic1[NI * D];
__device__ float  g_ic2[NI * D];
__device__ float  g_rw[LAYERS * NR * D];
__device__ float  g_rb[LAYERS * NR];
__device__ float  g_wat[LAYERS * D * D];
__device__ float  g_wbt[LAYERS * D * D];
__device__ float  g_bsum[LAYERS * D];
__device__ float  g_acc;
// fp16 mirrors
__device__ __half g_h_uemb[NU * D];
__device__ __half g_h_iemb[NI * D];
__device__ __half g_h_eemb[NE * D];
__device__ __half g_h_aggu0[NU * D];
__device__ __half g_h_ic1[NI * D];
// CSR scratch (g_cnt zero-initialized at load; layer-0 gathers re-zero it)
__device__ int    g_cnt[NSEG];
__device__ int    g_off[NSEG + 1];
__device__ int    g_bs_i[256];
__device__ int    g_bs_u[256];
__device__ int2   g_csr[2 * EDGES];

// ---------------- fused fp32 -> fp16 conversion --------------------------------
#define N4_U (NU * D / 4)
#define N4_I (NI * D / 4)
#define N4_E (NE * D / 4)
#define N4_ALL (N4_U + N4_I + N4_E)
__global__ void k_tohalf(const float4* __restrict__ u, __half* __restrict__ hu,
                         const float4* __restrict__ i, __half* __restrict__ hi,
                         const float4* __restrict__ e, __half* __restrict__ he) {
    int x = blockIdx.x * 256 + threadIdx.x;
    const float4* in;
    __half* out;
    if (x < N4_U) { in = u + x; out = hu + x * 4; }
    else if (x < N4_U + N4_I) { int y = x - N4_U; in = i + y; out = hi + y * 4; }
    else if (x < N4_ALL) { int y = x - N4_U - N4_I; in = e + y; out = he + y * 4; }
    else return;
    float4 v = *in;
    __half2 a = __floats2half2_rn(v.x, v.y);
    __half2 b = __floats2half2_rn(v.z, v.w);
    uint2 o;
    o.x = *(unsigned*)&a; o.y = *(unsigned*)&b;
    *(uint2*)out = o;
}

// ---------------- split CSR histograms: fire-and-forget RED, MLP=4 -------------
#define EB4 ((EDGES / 4 + 255) / 256)
__global__ void k_hist_i(const int* __restrict__ ei, int* __restrict__ cnt) {
    int base = (blockIdx.x * 256 + threadIdx.x) * 4;
    int idx[4];
#pragma unroll
    for (int k = 0; k < 4; k++) {
        int e = base + k;
        idx[k] = (e < EDGES) ? ei[e] : -1;
    }
#pragma unroll
    for (int k = 0; k < 4; k++)
        if (idx[k] >= 0) atomicAdd(&cnt[idx[k]], 1);
}

__global__ void k_hist_u(const int* __restrict__ eu, int* __restrict__ cnt) {
    int base = (blockIdx.x * 256 + threadIdx.x) * 4;
    int idx[4];
#pragma unroll
    for (int k = 0; k < 4; k++) {
        int e = base + k;
        idx[k] = (e < EDGES) ? eu[e] : -1;
    }
#pragma unroll
    for (int k = 0; k < 4; k++)
        if (idx[k] >= 0) atomicAdd(&cnt[NI + idx[k]], 1);
}

// ---------------- partial scan: off + cursor init (cnt <- off) -----------------
__global__ void k_scan_part(int* __restrict__ cnt, int* __restrict__ off,
                            int* __restrict__ bs,
                            int start, int n, int base, int endval) {
    __shared__ int sh[1024];
    __shared__ int s_prefix;
    int b = blockIdx.x;
    int gid = b * 1024 + threadIdx.x;
    int v = gid < n ? cnt[start + gid] : 0;
    sh[threadIdx.x] = v;
    __syncthreads();
#pragma unroll
    for (int d = 1; d < 1024; d <<= 1) {
        int t = threadIdx.x >= d ? sh[threadIdx.x - d] : 0;
        __syncthreads();
        sh[threadIdx.x] += t;
        __syncthreads();
    }
    if (threadIdx.x == 1023) atomicExch(&bs[b], sh[1023] + 1);

    if (threadIdx.x < 32) {
        int lane = threadIdx.x;
        int sum = 0;
        volatile int* vbs = (volatile int*)bs;
        for (int i = b - 1 - lane; i >= 0; i -= 32) {
            int got;
            do { got = vbs[i]; } while (got == 0);
            sum += got - 1;
        }
#pragma unroll
        for (int o = 16; o; o >>= 1) sum += __shfl_xor_sync(0xffffffffu, sum, o);
        if (lane == 0) s_prefix = sum;
    }
    __syncthreads();
    if (gid < n) {
        int val = base + s_prefix + sh[threadIdx.x] - v;
        off[start + gid] = val;
        cnt[start + gid] = val;       // cursor for fill
    }
    if (gid == 0) off[start + n] = endval;
}

// ---------------- split CSR fills: atomic-cursor position, MLP=4 ----------------
__global__ void k_fill_i(const int* __restrict__ eu, const int* __restrict__ ei,
                         const float* __restrict__ enorm,
                         int* __restrict__ cur,
                         int2* __restrict__ csr, int* __restrict__ bs) {
    if (blockIdx.x == 0 && threadIdx.x < 256) bs[threadIdx.x] = 0;
    int base = (blockIdx.x * 256 + threadIdx.x) * 4;
    int dsts[4], srcs[4];
    float nrms[4];
#pragma unroll
    for (int k = 0; k < 4; k++) {
        int e = base + k;
        if (e < EDGES) {
            dsts[k] = ei[e];
            srcs[k] = eu[e];
            nrms[k] = enorm[e];
        } else dsts[k] = -1;
    }
    int pos[4];
#pragma unroll
    for (int k = 0; k < 4; k++)
        if (dsts[k] >= 0) pos[k] = atomicAdd(&cur[dsts[k]], 1);
#pragma unroll
    for (int k = 0; k < 4; k++) {
        if (dsts[k] < 0) continue;
        int2 a;
        a.x = srcs[k];
        a.y = __float_as_int(nrms[k]);
        csr[pos[k]] = a;
    }
}

__global__ void k_fill_u(const int* __restrict__ eu, const int* __restrict__ ei,
                         const float* __restrict__ enorm,
                         int* __restrict__ cur,
                         int2* __restrict__ csr, int* __restrict__ bs) {
    if (blockIdx.x == 0 && threadIdx.x < 256) bs[threadIdx.x] = 0;
    int base = (blockIdx.x * 256 + threadIdx.x) * 4;
    int dsts[4], srcs[4];
    float nrms[4];
#pragma unroll
    for (int k = 0; k < 4; k++) {
        int e = base + k;
        if (e < EDGES) {
            dsts[k] = eu[e];
            srcs[k] = ei[e];
            nrms[k] = enorm[e];
        } else dsts[k] = -1;
    }
    int pos[4];
#pragma unroll
    for (int k = 0; k < 4; k++)
        if (dsts[k] >= 0) pos[k] = atomicAdd(&cur[NI + dsts[k]], 1);
#pragma unroll
    for (int k = 0; k < 4; k++) {
        if (dsts[k] < 0) continue;
        int2 a;
        a.x = srcs[k];
        a.y = __float_as_int(nrms[k]);
        csr[pos[k]] = a;
    }
}

// ---------------- rw precompute + gate weight transpose ------------------------
__global__ void k_rwprep(const float* __restrict__ remb,
                         const float* __restrict__ Wk_w,
                         const float* __restrict__ Wk_b,
                         const float* __restrict__ Wa_w,
                         const float* __restrict__ Wa_b,
                         const float* __restrict__ Wb_w,
                         const float* __restrict__ Wb_b,
                         float* __restrict__ rw, float* __restrict__ rb,
                         float* __restrict__ wat, float* __restrict__ wbt,
                         float* __restrict__ bsum, float* __restrict__ acc) {
    int b = blockIdx.x;
    if (b < LAYERS * NR) {
        if (threadIdx.x >= D) return;
        int l = b >> 6, rr = b & 63, d = threadIdx.x;
        const float* W = Wk_w + (size_t)l * D * 2 * D;
        const float* re = remb + rr * D;
        float a = 0.f;
#pragma unroll 8
        for (int o = 0; o < D; o++)
            a += re[o] * (W[o * 2 * D + d] + W[o * 2 * D + D + d]);
        rw[(l * NR + rr) * D + d] = a;
        if (d == 0) {
            const float* bb = Wk_b + l * D;
            float s = 0.f;
            for (int o = 0; o < D; o++) s += re[o] * bb[o];
            rb[l * NR + rr] = s;
        }
        if (b == 0 && d == 0) *acc = 0.f;
    } else {
        int i = (b - LAYERS * NR) * 256 + threadIdx.x;
        if (i >= LAYERS * D * D) return;
        int l = i >> 12, r = i & 4095, dd = r >> 6, o = r & 63;
        wat[i] = Wa_w[l * D * D + o * D + dd];
        wbt[i] = Wb_w[l * D * D + o * D + dd];
        if (r < D) bsum[l * D + r] = Wa_b[l * D + r] + Wb_b[l * D + r];
    }
}

// ---------------- gather core: 8 lanes/edge, 4-edge unroll (MLP=4) -------------
__device__ __forceinline__ void gaccv(uint4 hv, float nrm, float* acc) {
    float2 f0 = __half22float2(*(__half2*)&hv.x);
    float2 f1 = __half22float2(*(__half2*)&hv.y);
    float2 f2 = __half22float2(*(__half2*)&hv.z);
    float2 f3 = __half22float2(*(__half2*)&hv.w);
    acc[0] += nrm * f0.x; acc[1] += nrm * f0.y;
    acc[2] += nrm * f1.x; acc[3] += nrm * f1.y;
    acc[4] += nrm * f2.x; acc[5] += nrm * f2.y;
    acc[6] += nrm * f3.x; acc[7] += nrm * f3.y;
}

__device__ __forceinline__ void gather_seg(const __half* __restrict__ src,
                                           const int2* __restrict__ csr,
                                           int s, int e, int g, int sub,
                                           float* acc) {
    int t = s + g;
    for (; t + 12 < e; t += 16) {
        int2 p0 = __ldg(&csr[t]);
        int2 p1 = __ldg(&csr[t + 4]);
        int2 p2 = __ldg(&csr[t + 8]);
        int2 p3 = __ldg(&csr[t + 12]);
        uint4 r0 = *(const uint4*)(src + (size_t)p0.x * D + sub * 8);
        uint4 r1 = *(const uint4*)(src + (size_t)p1.x * D + sub * 8);
        uint4 r2 = *(const uint4*)(src + (size_t)p2.x * D + sub * 8);
        uint4 r3 = *(const uint4*)(src + (size_t)p3.x * D + sub * 8);
        gaccv(r0, __int_as_float(p0.y), acc);
        gaccv(r1, __int_as_float(p1.y), acc);
        gaccv(r2, __int_as_float(p2.y), acc);
        gaccv(r3, __int_as_float(p3.y), acc);
    }
    if (t + 4 < e) {
        int2 p0 = __ldg(&csr[t]);
        int2 p1 = __ldg(&csr[t + 4]);
        uint4 r0 = *(const uint4*)(src + (size_t)p0.x * D + sub * 8);
        uint4 r1 = *(const uint4*)(src + (size_t)p1.x * D + sub * 8);
        gaccv(r0, __int_as_float(p0.y), acc);
        gaccv(r1, __int_as_float(p1.y), acc);
        t += 8;
    }
    if (t < e) {
        int2 p0 = __ldg(&csr[t]);
        uint4 r0 = *(const uint4*)(src + (size_t)p0.x * D + sub * 8);
        gaccv(r0, __int_as_float(p0.y), acc);
    }
}

__device__ __forceinline__ void gather_reduce(float* acc) {
#pragma unroll
    for (int k = 0; k < 8; k++) {
        acc[k] += __shfl_xor_sync(0xffffffffu, acc[k], 8);
        acc[k] += __shfl_xor_sync(0xffffffffu, acc[k], 16);
    }
}

// ---------------- layer-0 gathers (also re-zero cnt for next launch) -----------
__global__ void k_gather_i(const __half* __restrict__ usrc,
                           const int2* __restrict__ csr,
                           const int* __restrict__ off,
                           float* __restrict__ aggi,
                           int* __restrict__ cnt) {
    int w = (blockIdx.x * blockDim.x + threadIdx.x) >> 5;
    int lane = threadIdx.x & 31;
    if (w >= NI) return;
    if (lane == 0) cnt[w] = 0;
    float acc[8];
#pragma unroll
    for (int k = 0; k < 8; k++) acc[k] = 0.f;
    gather_seg(usrc, csr, off[w], off[w + 1], lane >> 3, lane & 7, acc);
    gather_reduce(acc);
    if (lane < 8) {
        float* out = aggi + (size_t)w * D;
        float4 a; a.x = acc[0]; a.y = acc[1]; a.z = acc[2]; a.w = acc[3];
        float4 b; b.x = acc[4]; b.y = acc[5]; b.z = acc[6]; b.w = acc[7];
        *(float4*)(out + lane * 8) = a;
        *(float4*)(out + lane * 8 + 4) = b;
    }
}

// user gather: fp16 output only (fp32 aggu0 eliminated)
__global__ void k_gather_u(const __half* __restrict__ isrc,
                           const int2* __restrict__ csr,
                           const int* __restrict__ off,
                           __half* __restrict__ h_aggu,
                           int* __restrict__ cnt) {
    int w = (blockIdx.x * blockDim.x + threadIdx.x) >> 5;
    int lane = threadIdx.x & 31;
    if (w >= NU) return;
    if (lane == 0) cnt[NI + w] = 0;
    float acc[8];
#pragma unroll
    for (int k = 0; k < 8; k++) acc[k] = 0.f;
    gather_seg(isrc, csr, off[NI + w], off[NI + w + 1], lane >> 3, lane & 7, acc);
    gather_reduce(acc);
    if (lane < 8) {
        __half2 h0 = __floats2half2_rn(acc[0], acc[1]);
        __half2 h1 = __floats2half2_rn(acc[2], acc[3]);
        __half2 h2 = __floats2half2_rn(acc[4], acc[5]);
        __half2 h3 = __floats2half2_rn(acc[6], acc[7]);
        uint4 o;
        o.x = *(unsigned*)&h0; o.y = *(unsigned*)&h1;
        o.z = *(unsigned*)&h2; o.w = *(unsigned*)&h3;
        *(uint4*)(h_aggu + (size_t)w * D + lane * 8) = o;
    }
}

// ---------------- KG attention core ---------------------------------------------
__device__ __forceinline__ void attn_item(int item,
                                          const float* __restrict__ icur,
                                          const __half* __restrict__ eemb,
                                          const int* __restrict__ kg_ent,
                                          const int* __restrict__ kg_rel,
                                          const float* __restrict__ rw,
                                          const float* __restrict__ rb,
                                          float* __restrict__ kg_out,
                                          int lane) {
    float2 ic = *(const float2*)(icur + (size_t)item * D + lane * 2);
    float2 v[KNB];
    float sc[KNB];
    int base = item * KNB;
#pragma unroll
    for (int k = 0; k < KNB; k++) {
        int e = __ldg(&kg_ent[base + k]);
        int rr = __ldg(&kg_rel[base + k]);
        __half2 hv = *(const __half2*)(eemb + (size_t)e * D + lane * 2);
        v[k] = __half22float2(hv);
        float2 w = *(const float2*)(rw + rr * D + lane * 2);
        float p = v[k].x * ic.x * w.x + v[k].y * ic.y * w.y;
#pragma unroll
        for (int off = 16; off; off >>= 1) p += __shfl_xor_sync(0xffffffffu, p, off);
        p += __ldg(&rb[rr]);
        sc[k] = p >= 0.f ? p : 0.2f * p;
    }
    float m = sc[0];
#pragma unroll
    for (int k = 1; k < KNB; k++) m = fmaxf(m, sc[k]);
    float s = 0.f;
#pragma unroll
    for (int k = 0; k < KNB; k++) { sc[k] = __expf(sc[k] - m); s += sc[k]; }
    float inv = 1.f / s;
    float ax = 0.f, ay = 0.f;
#pragma unroll
    for (int k = 0; k < KNB; k++) {
        float a = sc[k] * inv;
        ax += a * v[k].x;
        ay += a * v[k].y;
    }
    float2 o;
    o.x = ax; o.y = ay;
    *(float2*)(kg_out + (size_t)item * D + lane * 2) = o;
}

__global__ void k_attn(const float* __restrict__ icur,
                       const __half* __restrict__ eemb,
                       const int* __restrict__ kg_ent,
                       const int* __restrict__ kg_rel,
                       const float* __restrict__ rw,
                       const float* __restrict__ rb,
                       float* __restrict__ kg_out) {
    int tid = threadIdx.x;
    int item = blockIdx.x * 8 + (tid >> 5);
    if (item >= NI) return;
    attn_item(item, icur, eemb, kg_ent, kg_rel, rw, rb, kg_out, tid & 31);
}

// ---------------- fused layer-1: batch-restricted gather + attention -------------
#define L1_GB ((NSUB + 7) / 8)
#define L1_AB ((2 * BB + 7) / 8)
__global__ void k_l1(const __half* __restrict__ husrc,
                     const __half* __restrict__ hisrc,
                     const int2* __restrict__ csr,
                     const int* __restrict__ off,
                     const int* __restrict__ pos,
                     const int* __restrict__ neg,
                     const int* __restrict__ user,
                     float* __restrict__ aggu,
                     float* __restrict__ aggi,
                     const float* __restrict__ icur,
                     const __half* __restrict__ eemb,
                     const int* __restrict__ kg_ent,
                     const int* __restrict__ kg_rel,
                     const float* __restrict__ rw,
                     const float* __restrict__ rb,
                     float* __restrict__ kg_out) {
    int tid = threadIdx.x;
    int warp = tid >> 5, lane = tid & 31;
    if (blockIdx.x < L1_GB) {
        int w = blockIdx.x * 8 + warp;
        if (w >= NSUB) return;
        const __half* src;
        float* out;
        int seg;
        if (w < 2 * BB) {
            int item = w < BB ? __ldg(&pos[w]) : __ldg(&neg[w - BB]);
            seg = item;
            src = husrc;
            out = aggi + (size_t)item * D;
        } else {
            int u = __ldg(&user[w - 2 * BB]);
            seg = NI + u;
            src = hisrc;
            out = aggu + (size_t)u * D;
        }
        float acc[8];
#pragma unroll
        for (int k = 0; k < 8; k++) acc[k] = 0.f;
        gather_seg(src, csr, off[seg], off[seg + 1], lane >> 3, lane & 7, acc);
        gather_reduce(acc);
        if (lane < 8) {
            float4 a; a.x = acc[0]; a.y = acc[1]; a.z = acc[2]; a.w = acc[3];
            float4 b; b.x = acc[4]; b.y = acc[5]; b.z = acc[6]; b.w = acc[7];
            *(float4*)(out + lane * 8) = a;
            *(float4*)(out + lane * 8 + 4) = b;
        }
    } else {
        int w = (blockIdx.x - L1_GB) * 8 + warp;
        if (w >= 2 * BB) return;
        int item = w < BB ? __ldg(&pos[w]) : __ldg(&neg[w - BB]);
        attn_item(item, icur, eemb, kg_ent, kg_rel, rw, rb, kg_out, lane);
    }
}

// ---------------- gate + item update ----------------------------------------------
#define G_ITEMS 64
#define G_PITCH 66
#define G_SMEM ((2 * D * G_PITCH + 2 * G_ITEMS * D + D) * sizeof(float))

template <bool SUB>
__device__ __forceinline__ void gate_body(const float* __restrict__ kg,
                                          const float* __restrict__ aggi,
                                          const float* __restrict__ wat,
                                          const float* __restrict__ wbt,
                                          const float* __restrict__ bsum,
                                          float* __restrict__ inew,
                                          __half* __restrict__ hout,
                                          const int* __restrict__ pos,
                                          const int* __restrict__ neg) {
    extern __shared__ float sm[];
    float* sWa = sm;
    float* sWb = sWa + D * G_PITCH;
    float* skg = sWb + D * G_PITCH;
    float* sag = skg + G_ITEMS * D;
    float* sb  = sag + G_ITEMS * D;
    __shared__ int sidx[G_ITEMS];

    int tid = threadIdx.x;
    int base = blockIdx.x * G_ITEMS;

    for (int i = tid; i < D * D; i += 256) {
        int dd = i >> 6, o = i & 63;
        sWa[dd * G_PITCH + o] = wat[i];
        sWb[dd * G_PITCH + o] = wbt[i];
    }
    if (tid < D) sb[tid] = bsum[tid];
    if (tid < G_ITEMS) {
        int j = base + tid;
        int gidx;
        if (SUB) gidx = j < BB ? __ldg(&pos[j]) : __ldg(&neg[j - BB]);
        else { gidx = j; if (gidx >= NI) gidx = NI - 1; }
        sidx[tid] = gidx;
    }
    __syncthreads();

    for (int i = tid; i < G_ITEMS * (D / 4); i += 256) {
        int it = i >> 4, c = i & 15;
        int gidx = sidx[it];
        ((float4*)skg)[it * 16 + c] = ((const float4*)kg)[(size_t)gidx * 16 + c];
        ((float4*)sag)[it * 16 + c] = ((const float4*)aggi)[(size_t)gidx * 16 + c];
    }
    __syncthreads();

    int warp = tid >> 5, lane = tid & 31;
    float2 acc[8];
#pragma unroll
    for (int j = 0; j < 8; j++) { acc[j].x = 0.f; acc[j].y = 0.f; }

    for (int d = 0; d < D; d += 2) {
        float2 wa0 = *(const float2*)(sWa + d * G_PITCH + 2 * lane);
        float2 wa1 = *(const float2*)(sWa + (d + 1) * G_PITCH + 2 * lane);
        float2 wb0 = *(const float2*)(sWb + d * G_PITCH + 2 * lane);
        float2 wb1 = *(const float2*)(sWb + (d + 1) * G_PITCH + 2 * lane);
#pragma unroll
        for (int j = 0; j < 8; j++) {
            int it = warp * 8 + j;
            float2 xk = *(const float2*)(skg + it * D + d);
            float2 xa = *(const float2*)(sag + it * D + d);
            acc[j].x += xk.x * wa0.x + xk.y * wa1.x + xa.x * wb0.x + xa.y * wb1.x;
            acc[j].y += xk.x * wa0.y + xk.y * wa1.y + xa.x * wb0.y + xa.y * wb1.y;
        }
    }

    float2 b2 = *(const float2*)(sb + 2 * lane);
#pragma unroll
    for (int j = 0; j < 8; j++) {
        int it = warp * 8 + j;
        if (!SUB && base + it >= NI) break;
        float gx = 1.f / (1.f + __expf(-(acc[j].x + b2.x)));
        float gy = 1.f / (1.f + __expf(-(acc[j].y + b2.y)));
        float2 kv = *(const float2*)(skg + it * D + 2 * lane);
        float2 av = *(const float2*)(sag + it * D + 2 * lane);
        float2 o2;
        o2.x = gx * kv.x + (1.f - gx) * av.x;
        o2.y = gy * kv.y + (1.f - gy) * av.y;
        int gidx = sidx[it];
        ((float2*)(inew + (size_t)gidx * D))[lane] = o2;
        if (!SUB && hout != nullptr) {
            __half2 h = __floats2half2_rn(o2.x, o2.y);
            ((__half2*)(hout + (size_t)gidx * D))[lane] = h;
        }
    }
}

__global__ void k_gate(const float* __restrict__ kg,
                       const float* __restrict__ aggi,
                       const float* __restrict__ wat,
                       const float* __restrict__ wbt,
                       const float* __restrict__ bsum,
                       float* __restrict__ inew,
                       __half* __restrict__ hout) {
    gate_body<false>(kg, aggi, wat, wbt, bsum, inew, hout, nullptr, nullptr);
}

__global__ void k_gate_sub(const float* __restrict__ kg,
                           const float* __restrict__ aggi,
                           const float* __restrict__ wat,
                           const float* __restrict__ wbt,
                           const float* __restrict__ bsum,
                           float* __restrict__ inew,
                           const int* __restrict__ pos,
                           const int* __restrict__ neg) {
    gate_body<true>(kg, aggi, wat, wbt, bsum, inew, nullptr, pos, neg);
}

// ---------------- loss (aggu0 read from fp16 mirror) -----------------------------
__global__ void k_loss(const float* __restrict__ uemb,
                       const __half* __restrict__ h_aggu0,
                       const float* __restrict__ aggu1,
                       const float* __restrict__ iemb,
                       const float* __restrict__ ic1,
                       const float* __restrict__ ic2,
                       const int* __restrict__ user,
                       const int* __restrict__ pos,
                       const int* __restrict__ neg,
                       float* __restrict__ acc) {
    int b = (blockIdx.x * blockDim.x + threadIdx.x) >> 5;
    int lane = threadIdx.x & 31;
    if (b >= BB) return;
    size_t u = (size_t)user[b] * D;
    size_t p = (size_t)pos[b] * D;
    size_t n = (size_t)neg[b] * D;

    int d = lane * 2;
    float2 ua = *(const float2*)(uemb + u + d);
    float2 ub = __half22float2(*(const __half2*)(h_aggu0 + u + d));
    float2 uc = *(const float2*)(aggu1 + u + d);
    float2 pa = *(const float2*)(iemb + p + d);
    float2 pb = *(const float2*)(ic1 + p + d);
    float2 pc = *(const float2*)(ic2 + p + d);
    float2 na = *(const float2*)(iemb + n + d);
    float2 nb = *(const float2*)(ic1 + n + d);
    float2 nc = *(const float2*)(ic2 + n + d);
    float uex = ua.x + ub.x + uc.x, uey = ua.y + ub.y + uc.y;
    float pex = pa.x + pb.x + pc.x, pey = pa.y + pb.y + pc.y;
    float nex = na.x + nb.x + nc.x, ney = na.y + nb.y + nc.y;
    float ps = uex * pex + uey * pey;
    float ns = uex * nex + uey * ney;
    float l2 = uex * uex + uey * uey + pex * pex + pey * pey + nex * nex + ney * ney;
#pragma unroll
    for (int off = 16; off; off >>= 1) {
        ps += __shfl_xor_sync(0xffffffffu, ps, off);
        ns += __shfl_xor_sync(0xffffffffu, ns, off);
        l2 += __shfl_xor_sync(0xffffffffu, l2, off);
    }
    if (lane == 0) {
        float x = ps - ns;
        float sg = 1.f / (1.f + expf(-x));
        float term = -logf(sg + 1e-10f) + REG * l2;
        atomicAdd(acc, term);
    }
}

__global__ void k_final(const float* __restrict__ acc, float* __restrict__ out) {
    out[0] = acc[0] * (1.f / (float)BB);
}

// ---------------- launch ----------------------------------------------------------
extern "C" void kernel_launch(void* const* d_in, const int* in_sizes, int n_in,
                              void* d_out, int out_size) {
    const float* uemb  = (const float*)d_in[0];
    const float* iemb  = (const float*)d_in[1];
    const float* eemb  = (const float*)d_in[2];
    const float* remb  = (const float*)d_in[3];
    const float* Wk_w  = (const float*)d_in[4];
    const float* Wk_b  = (const float*)d_in[5];
    const float* Wa_w  = (const float*)d_in[6];
    const float* Wa_b  = (const float*)d_in[7];
    const float* Wb_w  = (const float*)d_in[8];
    const float* Wb_b  = (const float*)d_in[9];
    const float* enorm = (const float*)d_in[10];
    const int* user    = (const int*)d_in[11];
    const int* pos     = (const int*)d_in[12];
    const int* neg     = (const int*)d_in[13];
    const int* eu      = (const int*)d_in[14];
    const int* ei      = (const int*)d_in[15];
    const int* kg_rel  = (const int*)d_in[16];
    const int* kg_ent  = (const int*)d_in[17];

    float *agg, *kg, *ic1, *ic2, *rw, *rb, *wat, *wbt, *bsum, *acc;
    int *cnt, *off, *bs_i, *bs_u;
    int2 *csr;
    __half *h_uemb, *h_iemb, *h_eemb, *h_aggu0, *h_ic1;
    cudaGetSymbolAddress((void**)&agg, g_agg);
    cudaGetSymbolAddress((void**)&kg, g_kg);
    cudaGetSymbolAddress((void**)&ic1, g_ic1);
    cudaGetSymbolAddress((void**)&ic2, g_ic2);
    cudaGetSymbolAddress((void**)&rw, g_rw);
    cudaGetSymbolAddress((void**)&rb, g_rb);
    cudaGetSymbolAddress((void**)&wat, g_wat);
    cudaGetSymbolAddress((void**)&wbt, g_wbt);
    cudaGetSymbolAddress((void**)&bsum, g_bsum);
    cudaGetSymbolAddress((void**)&acc, g_acc);
    cudaGetSymbolAddress((void**)&cnt, g_cnt);
    cudaGetSymbolAddress((void**)&off, g_off);
    cudaGetSymbolAddress((void**)&bs_i, g_bs_i);
    cudaGetSymbolAddress((void**)&bs_u, g_bs_u);
    cudaGetSymbolAddress((void**)&csr, g_csr);
    cudaGetSymbolAddress((void**)&h_uemb, g_h_uemb);
    cudaGetSymbolAddress((void**)&h_iemb, g_h_iemb);
    cudaGetSymbolAddress((void**)&h_eemb, g_h_eemb);
    cudaGetSymbolAddress((void**)&h_aggu0, g_h_aggu0);
    cudaGetSymbolAddress((void**)&h_ic1, g_h_ic1);

    float* aggu1 = agg;
    float* aggi0 = agg + (size_t)NU * D;
    float* aggi1 = agg + (size_t)NU * D + (size_t)NI * D;

    cudaFuncSetAttribute(k_gate, cudaFuncAttributeMaxDynamicSharedMemorySize,
                         (int)G_SMEM);
    cudaFuncSetAttribute(k_gate_sub, cudaFuncAttributeMaxDynamicSharedMemorySize,
                         (int)G_SMEM);

    static cudaStream_t s1 = nullptr, s2 = nullptr, s3 = nullptr;
    static cudaEvent_t e_fork, e_th, e_attn, e_gu, e_done;
    if (s1 == nullptr) {
        cudaStreamCreateWithFlags(&s1, cudaStreamNonBlocking);
        cudaStreamCreateWithFlags(&s2, cudaStreamNonBlocking);
        cudaStreamCreateWithFlags(&s3, cudaStreamNonBlocking);
        cudaEventCreateWithFlags(&e_fork, cudaEventDisableTiming);
        cudaEventCreateWithFlags(&e_th, cudaEventDisableTiming);
        cudaEventCreateWithFlags(&e_attn, cudaEventDisableTiming);
        cudaEventCreateWithFlags(&e_gu, cudaEventDisableTiming);
        cudaEventCreateWithFlags(&e_done, cudaEventDisableTiming);
    }

    // ---- fork ----
    cudaEventRecord(e_fork, 0);
    cudaStreamWaitEvent(s1, e_fork, 0);
    cudaStreamWaitEvent(s2, e_fork, 0);
    cudaStreamWaitEvent(s3, e_fork, 0);

    // ---- s3: embeddings/weights arm ----
    k_tohalf<<<(N4_ALL + 255) / 256, 256, 0, s3>>>(
        (const float4*)uemb, h_uemb,
        (const float4*)iemb, h_iemb,
        (const float4*)eemb, h_eemb);
    cudaEventRecord(e_th, s3);
    k_rwprep<<<LAYERS * NR + (LAYERS * D * D + 255) / 256, 256, 0, s3>>>(
        remb, Wk_w, Wk_b, Wa_w, Wa_b, Wb_w, Wb_b, rw, rb, wat, wbt, bsum, acc);
    k_attn<<<(NI + 7) / 8, 256, 0, s3>>>(iemb, h_eemb, kg_ent, kg_rel, rw, rb, kg);
    cudaEventRecord(e_attn, s3);

    // ---- s1: item-half CSR -> item gather ----
    k_hist_i<<<EB4, 256, 0, s1>>>(ei, cnt);
    k_scan_part<<<SCAN_I_BLOCKS, 1024, 0, s1>>>(cnt, off, bs_i, 0, NI, 0, EDGES);
    k_fill_i<<<EB4, 256, 0, s1>>>(eu, ei, enorm, cnt, csr, bs_i);
    cudaStreamWaitEvent(s1, e_th, 0);
    k_gather_i<<<(NI + 7) / 8, 256, 0, s1>>>(h_uemb, csr, off, aggi0, cnt);

    // ---- s2: user-half CSR -> user gather ----
    k_hist_u<<<EB4, 256, 0, s2>>>(eu, cnt);
    k_scan_part<<<SCAN_U_BLOCKS, 1024, 0, s2>>>(cnt, off, bs_u, NI, NU,
                                                EDGES, 2 * EDGES);
    k_fill_u<<<EB4, 256, 0, s2>>>(eu, ei, enorm, cnt, csr, bs_u);
    cudaStreamWaitEvent(s2, e_th, 0);
    k_gather_u<<<(NU + 7) / 8, 256, 0, s2>>>(h_iemb, csr, off, h_aggu0, cnt);
    cudaEventRecord(e_gu, s2);

    // ---- join on s1: gate0 (needs aggi0 + kg) ----
    cudaStreamWaitEvent(s1, e_attn, 0);
    k_gate<<<(NI + G_ITEMS - 1) / G_ITEMS, 256, G_SMEM, s1>>>(
        kg, aggi0, wat, wbt, bsum, ic1, h_ic1);
    cudaStreamWaitEvent(s1, e_gu, 0);
    k_l1<<<L1_GB + L1_AB, 256, 0, s1>>>(h_aggu0, h_ic1, csr, off, pos, neg, user,
                                        aggu1, aggi1,
                                        ic1, h_eemb, kg_ent, kg_rel,
                                        rw + NR * D, rb + NR, kg);
    k_gate_sub<<<2 * BB / G_ITEMS, 256, G_SMEM, s1>>>(kg, aggi1,
                                                      wat + D * D, wbt + D * D,
                                                      bsum + D, ic2, pos, neg);
    k_loss<<<(BB * 32 + 255) / 256, 256, 0, s1>>>(uemb, h_aggu0, aggu1,
                                                  iemb, ic1, ic2,
                                                  user, pos, neg, acc);
    k_final<<<1, 1, 0, s1>>>(acc, (float*)d_out);
    cudaEventRecord(e_done, s1);

    // ---- join back to caller's stream ----
    cudaStreamWaitEvent(0, e_done, 0);
}